// round 14
// baseline (speedup 1.0000x reference)
#include <cuda_runtime.h>
#include <cuda_fp16.h>
#include <cstdint>

#define MM 16384
#define DD 1024
#define NN 1024
#define KCP 34

// Chunk-contiguous, XOR-swizzled split-fp16 operands, k=16 chunks.
// Tile = 128 rows x 64B (8KB). Row r: 4 granules of 16B at (g ^ ((r>>1)&3))*16.
// g0,g1 = hi halves (k0-7, k8-15); g2,g3 = lo halves.
__device__ __half A3_buf[(size_t)MM * 2 * DD];   // 64 MB: [mtile(128)][chunk(64)][8KB]
__device__ __half B3_buf[(size_t)NN * 2 * DD];   // 4 MB:  [ntile(8)][chunk(64)][8KB]

__device__ __forceinline__ uint32_t s2u(const void* p) {
    uint32_t a;
    asm("{ .reg .u64 t; cvta.to.shared.u64 t, %1; cvt.u32.u64 %0, t; }" : "=r"(a) : "l"(p));
    return a;
}

#define LDSM4(r, a) \
    asm volatile("ldmatrix.sync.aligned.m8n8.x4.shared.b16 {%0,%1,%2,%3}, [%4];" \
                 : "=r"((r)[0]), "=r"((r)[1]), "=r"((r)[2]), "=r"((r)[3]) : "r"(a))

#define MMA16816(c, a, b0, b1) \
    asm("mma.sync.aligned.m16n8k16.row.col.f32.f16.f16.f32 " \
        "{%0,%1,%2,%3}, {%4,%5,%6,%7}, {%8,%9}, {%0,%1,%2,%3};" \
        : "+f"((c).x), "+f"((c).y), "+f"((c).z), "+f"((c).w) \
        : "r"((a)[0]), "r"((a)[1]), "r"((a)[2]), "r"((a)[3]), "r"(b0), "r"(b1))

// ---------------- vectorized convert kernels ----------------
__device__ __forceinline__ void split8(const float4 f0, const float4 f1,
                                       uint4& hi, uint4& lo)
{
    const float v[8] = {f0.x, f0.y, f0.z, f0.w, f1.x, f1.y, f1.z, f1.w};
    __half h[8], l[8];
    #pragma unroll
    for (int i = 0; i < 8; ++i) {
        h[i] = __float2half_rn(v[i]);
        l[i] = __float2half_rn(v[i] - __half2float(h[i]));
    }
    hi = *reinterpret_cast<const uint4*>(h);
    lo = *reinterpret_cast<const uint4*>(l);
}

__global__ __launch_bounds__(256) void convert_A(const float* __restrict__ X)
{
    int t = blockIdx.x * blockDim.x + threadIdx.x;   // MM*128 threads
    int m  = t >> 7;
    int j  = t & 127;
    int kb = j >> 1;           // chunk (0..63), k=16 each
    int g  = j & 1;            // hi granule (0..1)
    const float4* src = reinterpret_cast<const float4*>(X + (size_t)m * DD + kb * 16 + g * 8);
    uint4 hi, lo;
    split8(src[0], src[1], hi, lo);
    int tile = m >> 7, r = m & 127, xk = (r >> 1) & 3;
    char* base = reinterpret_cast<char*>(A3_buf) + ((size_t)(tile * 64 + kb)) * 8192 + r * 64;
    *reinterpret_cast<uint4*>(base + ((g ^ xk) * 16))       = hi;
    *reinterpret_cast<uint4*>(base + (((g + 2) ^ xk) * 16)) = lo;
}

__global__ __launch_bounds__(256) void convert_B(const float* __restrict__ W)
{
    int t = blockIdx.x * blockDim.x + threadIdx.x;   // NN*128 threads
    int n    = t & 1023;
    int rest = t >> 10;
    int kb = rest >> 1;
    int g  = rest & 1;
    int k0 = kb * 16 + g * 8;
    float v[8];
    #pragma unroll
    for (int i = 0; i < 8; ++i)
        v[i] = W[(size_t)(k0 + i) * NN + n];          // warp-coalesced along n
    __half h[8], l[8];
    #pragma unroll
    for (int i = 0; i < 8; ++i) {
        h[i] = __float2half_rn(v[i]);
        l[i] = __float2half_rn(v[i] - __half2float(h[i]));
    }
    int tile = n >> 7, r = n & 127, xk = (r >> 1) & 3;
    char* base = reinterpret_cast<char*>(B3_buf) + ((size_t)(tile * 64 + kb)) * 8192 + r * 64;
    *reinterpret_cast<uint4*>(base + ((g ^ xk) * 16))       = *reinterpret_cast<const uint4*>(h);
    *reinterpret_cast<uint4*>(base + (((g + 2) ^ xk) * 16)) = *reinterpret_cast<const uint4*>(l);
}

// ---------------- fused GEMM + spline ----------------
// Tile 128x128, 4 stages of k=16. SMEM: cps 17920 | 4 A stages 8KB | 4 B stages 8KB | mbar.
#define CHUNK_B     8192
#define NCHUNKS     64
#define SOFF_A      17920
#define SOFF_B      (17920 + 4 * CHUNK_B)
#define SOFF_MBAR   (17920 + 8 * CHUNK_B)                 // FULL[4]@+0..24, EMPTY[4]@+32..56
#define SMEM_TOTAL  (SOFF_MBAR + 64)                      // 83520 -> 2 CTAs/SM

__device__ __forceinline__ float spline_eval(float s, const float* __restrict__ q)
{
    float t = s * 4.0f;
    float u = t - floorf(t);
    float pf = floorf((s + 4.0f) * 3.75f + 1.0f);
    if (s <= -4.0f) pf = 1.0f;
    if (s >=  4.0f) pf = 31.0f;
    int p0 = (int)pf;
    p0 = max(1, min(31, p0));
    float Q0 = q[p0 - 1];
    float Q1 = q[p0];
    float Q2 = q[p0 + 1];
    float Q3 = q[p0 + 2];
    float c3 = 3.0f * (Q1 - Q2) + (Q3 - Q0);
    float c2 = 2.0f * Q0 - 5.0f * Q1 + 4.0f * Q2 - Q3;
    float c1 = Q2 - Q0;
    float c0 = 2.0f * Q1;
    return 0.5f * (((c3 * u + c2) * u + c1) * u + c0);
}

__device__ __forceinline__ void mbar_init(uint32_t mbar, uint32_t cnt) {
    asm volatile("mbarrier.init.shared.b64 [%0], %1;" :: "r"(mbar), "r"(cnt) : "memory");
}
__device__ __forceinline__ void mbar_expect(uint32_t mbar, uint32_t bytes) {
    asm volatile("mbarrier.arrive.expect_tx.shared.b64 _, [%0], %1;" :: "r"(mbar), "r"(bytes) : "memory");
}
__device__ __forceinline__ void mbar_arrive(uint32_t mbar) {
    asm volatile("mbarrier.arrive.shared.b64 _, [%0];" :: "r"(mbar) : "memory");
}
__device__ __forceinline__ void mbar_wait_acq(uint32_t mbar, uint32_t parity) {
    asm volatile(
        "{\n\t.reg .pred P;\n\t"
        "LW%=:\n\t"
        "mbarrier.try_wait.parity.acquire.cta.shared::cta.b64 P, [%0], %1, 0x989680;\n\t"
        "@P bra.uni LD%=;\n\t"
        "bra.uni LW%=;\n\t"
        "LD%=:\n\t}"
        :: "r"(mbar), "r"(parity) : "memory");
}
__device__ __forceinline__ void mbar_wait_rlx(uint32_t mbar, uint32_t parity) {
    asm volatile(
        "{\n\t.reg .pred P;\n\t"
        "LW%=:\n\t"
        "mbarrier.try_wait.parity.relaxed.cta.shared::cta.b64 P, [%0], %1, 0x989680;\n\t"
        "@P bra.uni LD%=;\n\t"
        "bra.uni LW%=;\n\t"
        "LD%=:\n\t}"
        :: "r"(mbar), "r"(parity) : "memory");
}
__device__ __forceinline__ void bulk_g2s(uint32_t dst, const void* src, uint32_t bytes, uint32_t mbar) {
    asm volatile("cp.async.bulk.shared::cluster.global.mbarrier::complete_tx::bytes [%0], [%1], %2, [%3];"
                 :: "r"(dst), "l"(src), "r"(bytes), "r"(mbar) : "memory");
}

__global__ __launch_bounds__(256, 2) void gemm_spline(const float* __restrict__ CP,
                                                      float* __restrict__ out)
{
    extern __shared__ char smem[];
    float* cps = reinterpret_cast<float*>(smem);
    const uint32_t su = s2u(smem);
    const uint32_t FULL  = su + SOFF_MBAR;        // +8*s
    const uint32_t EMPTY = su + SOFF_MBAR + 32;   // +8*s

    const int tid  = threadIdx.x;
    const int lane = tid & 31;
    const int wid  = tid >> 5;
    const int bx = blockIdx.x;   // n tile (0..7)
    const int by = blockIdx.y;   // m tile (0..127)

    const char* Ag = reinterpret_cast<const char*>(A3_buf) + (size_t)by * NCHUNKS * CHUNK_B;
    const char* Bg = reinterpret_cast<const char*>(B3_buf) + (size_t)bx * NCHUNKS * CHUNK_B;

    if (tid == 0) {
        #pragma unroll
        for (int s = 0; s < 4; ++s) {
            mbar_init(FULL + 8 * s, 1);
            mbar_init(EMPTY + 8 * s, 8);
        }
        asm volatile("fence.proxy.async;" ::: "memory");
        #pragma unroll
        for (int s = 0; s < 4; ++s) {   // prologue: chunks 0..3
            mbar_expect(FULL + 8 * s, 2 * CHUNK_B);
            bulk_g2s(su + SOFF_A + s * CHUNK_B, Ag + (size_t)s * CHUNK_B, CHUNK_B, FULL + 8 * s);
            bulk_g2s(su + SOFF_B + s * CHUNK_B, Bg + (size_t)s * CHUNK_B, CHUNK_B, FULL + 8 * s);
        }
    }

    // stage control points (128 neurons, padded stride 35)
    for (int i = tid; i < 128 * KCP; i += 256) {
        int c = i / KCP, k = i - c * KCP;
        cps[c * 35 + k] = CP[(size_t)(bx * 128 + c) * KCP + k];
    }
    __syncthreads();

    float4 acc[4][4];
    #pragma unroll
    for (int i = 0; i < 4; ++i)
        #pragma unroll
        for (int j = 0; j < 4; ++j)
            acc[i][j] = make_float4(0.f, 0.f, 0.f, 0.f);

    const int mw = (wid >> 2) * 64;
    const int nw = (wid & 3) * 32;
    const int lrow = lane & 15;
    const int lcol = lane >> 4;
    const int xk = (lrow >> 1) & 3;    // 64B-row swizzle key
    const uint32_t gh = (uint32_t)((lcol ^ xk) * 16);
    const uint32_t gl = (uint32_t)(((lcol + 2) ^ xk) * 16);
    const uint32_t aRowB = su + SOFF_A + (mw + lrow) * 64;
    const uint32_t bRowB = su + SOFF_B + (nw + lrow) * 64;

    // Per chunk (k=16): wait FULL -> 12 LDSM -> arrive EMPTY -> producer refill -> 48 MMA.
    #define DO_CHUNK(S, CIDX, PH)                                                        \
    {                                                                                    \
        mbar_wait_acq(FULL + 8 * (S), (PH));                                             \
        const uint32_t aRow = aRowB + (S) * CHUNK_B;                                     \
        const uint32_t bRow = bRowB + (S) * CHUNK_B;                                     \
        uint32_t Ah[4][4], Al[4][4], Bh[2][4], Bl[2][4];                                 \
        _Pragma("unroll")                                                                \
        for (int mf = 0; mf < 4; ++mf) {                                                 \
            LDSM4(Ah[mf], aRow + mf * 1024 + gh);                                        \
            LDSM4(Al[mf], aRow + mf * 1024 + gl);                                        \
        }                                                                                \
        _Pragma("unroll")                                                                \
        for (int g = 0; g < 2; ++g) {                                                    \
            LDSM4(Bh[g], bRow + g * 1024 + gh);                                          \
            LDSM4(Bl[g], bRow + g * 1024 + gl);                                          \
        }                                                                                \
        if (lane == 0) mbar_arrive(EMPTY + 8 * (S));                                     \
        if (tid == 0 && (CIDX) + 4 < NCHUNKS) {                                          \
            mbar_wait_rlx(EMPTY + 8 * (S), (PH));                                        \
            mbar_expect(FULL + 8 * (S), 2 * CHUNK_B);                                    \
            bulk_g2s(su + SOFF_A + (S) * CHUNK_B,                                        \
                     Ag + (size_t)((CIDX) + 4) * CHUNK_B, CHUNK_B, FULL + 8 * (S));      \
            bulk_g2s(su + SOFF_B + (S) * CHUNK_B,                                        \
                     Bg + (size_t)((CIDX) + 4) * CHUNK_B, CHUNK_B, FULL + 8 * (S));      \
        }                                                                                \
        _Pragma("unroll")                                                                \
        for (int mf = 0; mf < 4; ++mf)                                                   \
            _Pragma("unroll")                                                            \
            for (int nf = 0; nf < 4; ++nf) {                                             \
                const int g = nf >> 1, w = nf & 1;                                       \
                MMA16816(acc[mf][nf], Ah[mf], Bh[g][w], Bh[g][w + 2]);                   \
                MMA16816(acc[mf][nf], Al[mf], Bh[g][w], Bh[g][w + 2]);                   \
                MMA16816(acc[mf][nf], Ah[mf], Bl[g][w], Bl[g][w + 2]);                   \
            }                                                                            \
    }

    #pragma unroll 1
    for (int p = 0; p < NCHUNKS / 4; ++p) {
        const uint32_t ph = (uint32_t)(p & 1);
        DO_CHUNK(0, 4 * p,     ph)
        DO_CHUNK(1, 4 * p + 1, ph)
        DO_CHUNK(2, 4 * p + 2, ph)
        DO_CHUNK(3, 4 * p + 3, ph)
    }
    #undef DO_CHUNK

    // epilogue: spline + store
    #pragma unroll
    for (int mf = 0; mf < 4; ++mf) {
        const int row0 = mw + mf * 16 + (lane >> 2);
        const size_t g0 = (size_t)(by * 128 + row0) * NN + bx * 128;
        const size_t g1 = g0 + 8 * NN;
        #pragma unroll
        for (int nf = 0; nf < 4; ++nf) {
            const int cl = nw + nf * 8 + 2 * (lane & 3);
            const float* q0 = &cps[cl * 35];
            const float* q1 = &cps[(cl + 1) * 35];
            float2 o0, o1;
            o0.x = spline_eval(acc[mf][nf].x, q0);
            o0.y = spline_eval(acc[mf][nf].y, q1);
            o1.x = spline_eval(acc[mf][nf].z, q0);
            o1.y = spline_eval(acc[mf][nf].w, q1);
            *reinterpret_cast<float2*>(out + g0 + cl) = o0;
            *reinterpret_cast<float2*>(out + g1 + cl) = o1;
        }
    }
}

extern "C" void kernel_launch(void* const* d_in, const int* in_sizes, int n_in,
                              void* d_out, int out_size)
{
    const float* X  = (const float*)d_in[0];
    const float* W  = (const float*)d_in[1];
    const float* CP = (const float*)d_in[2];
    float* out = (float*)d_out;

    cudaFuncSetAttribute(gemm_spline, cudaFuncAttributeMaxDynamicSharedMemorySize, SMEM_TOTAL);

    convert_A<<<(MM * 128) / 256, 256>>>(X);
    convert_B<<<(NN * 128) / 256, 256>>>(W);

    dim3 grid(NN / 128, MM / 128);   // (8, 128)
    gemm_spline<<<grid, 256, SMEM_TOTAL>>>(CP, out);
}

// round 15
// speedup vs baseline: 1.0913x; 1.0913x over previous
#include <cuda_runtime.h>
#include <cuda_fp16.h>
#include <cstdint>

#define MM 16384
#define DD 1024
#define NN 1024
#define KCP 34

// Chunk-contiguous, XOR-swizzled split-fp16 operands (R10 layout).
// tile = 128 rows x 128B; row r granule g (16B) at (g ^ (r&7))*16; g0..3 hi, g4..7 lo.
__device__ __half A3_buf[(size_t)MM * 2 * DD];   // 64 MB: [mtile(128)][chunk(32)][16KB]
__device__ __half B3_buf[(size_t)NN * 2 * DD];   // 4 MB:  [ntile(8)][chunk(32)][16KB]

__device__ __forceinline__ uint32_t s2u(const void* p) {
    uint32_t a;
    asm("{ .reg .u64 t; cvta.to.shared.u64 t, %1; cvt.u32.u64 %0, t; }" : "=r"(a) : "l"(p));
    return a;
}

#define LDSM4(r, a) \
    asm volatile("ldmatrix.sync.aligned.m8n8.x4.shared.b16 {%0,%1,%2,%3}, [%4];" \
                 : "=r"((r)[0]), "=r"((r)[1]), "=r"((r)[2]), "=r"((r)[3]) : "r"(a))

#define MMA16816(c, a, b0, b1) \
    asm("mma.sync.aligned.m16n8k16.row.col.f32.f16.f16.f32 " \
        "{%0,%1,%2,%3}, {%4,%5,%6,%7}, {%8,%9}, {%0,%1,%2,%3};" \
        : "+f"((c).x), "+f"((c).y), "+f"((c).z), "+f"((c).w) \
        : "r"((a)[0]), "r"((a)[1]), "r"((a)[2]), "r"((a)[3]), "r"(b0), "r"(b1))

// ---------------- vectorized convert kernels (R10 exact) ----------------
__device__ __forceinline__ void split8(const float4 f0, const float4 f1,
                                       uint4& hi, uint4& lo)
{
    const float v[8] = {f0.x, f0.y, f0.z, f0.w, f1.x, f1.y, f1.z, f1.w};
    __half h[8], l[8];
    #pragma unroll
    for (int i = 0; i < 8; ++i) {
        h[i] = __float2half_rn(v[i]);
        l[i] = __float2half_rn(v[i] - __half2float(h[i]));
    }
    hi = *reinterpret_cast<const uint4*>(h);
    lo = *reinterpret_cast<const uint4*>(l);
}

__global__ __launch_bounds__(256) void convert_A(const float* __restrict__ X)
{
    int t = blockIdx.x * blockDim.x + threadIdx.x;   // MM*128 threads
    int m  = t >> 7;
    int j  = t & 127;
    int kb = j >> 2;
    int g  = j & 3;
    const float4* src = reinterpret_cast<const float4*>(X + (size_t)m * DD + kb * 32 + g * 8);
    uint4 hi, lo;
    split8(src[0], src[1], hi, lo);
    int tile = m >> 7, r = m & 127, xk = r & 7;
    char* base = reinterpret_cast<char*>(A3_buf) + ((size_t)(tile * 32 + kb)) * 16384 + r * 128;
    *reinterpret_cast<uint4*>(base + ((g ^ xk) * 16))       = hi;
    *reinterpret_cast<uint4*>(base + (((g + 4) ^ xk) * 16)) = lo;
}

__global__ __launch_bounds__(256) void convert_B(const float* __restrict__ W)
{
    int t = blockIdx.x * blockDim.x + threadIdx.x;   // NN*128 threads
    int n    = t & 1023;
    int rest = t >> 10;
    int kb = rest >> 2;
    int g  = rest & 3;
    int k0 = kb * 32 + g * 8;
    float v[8];
    #pragma unroll
    for (int i = 0; i < 8; ++i)
        v[i] = W[(size_t)(k0 + i) * NN + n];
    __half h[8], l[8];
    #pragma unroll
    for (int i = 0; i < 8; ++i) {
        h[i] = __float2half_rn(v[i]);
        l[i] = __float2half_rn(v[i] - __half2float(h[i]));
    }
    int tile = n >> 7, r = n & 127, xk = r & 7;
    char* base = reinterpret_cast<char*>(B3_buf) + ((size_t)(tile * 32 + kb)) * 16384 + r * 128;
    *reinterpret_cast<uint4*>(base + ((g ^ xk) * 16))       = *reinterpret_cast<const uint4*>(h);
    *reinterpret_cast<uint4*>(base + (((g + 4) ^ xk) * 16)) = *reinterpret_cast<const uint4*>(l);
}

// ---------------- fused GEMM + spline ----------------
// 3 stages of k=32. SMEM: 3 A stages 16KB @0 | 3 B stages 16KB @49152 | mbar @98304.
// cps (17920 B) OVERLAYS the stage-A region after the mainloop (epilogue-only use).
#define TILE_BYTES  16384
#define SOFF_A      0
#define SOFF_B      (3 * TILE_BYTES)                       // 49152
#define SOFF_MBAR   (6 * TILE_BYTES)                       // 98304: FULL[3]@+0..16, EMPTY[3]@+24..40
#define SMEM_TOTAL  (SOFF_MBAR + 64)                       // 98368 -> 2 CTAs/SM

__device__ __forceinline__ float spline_eval(float s, const float* __restrict__ q)
{
    float t = s * 4.0f;
    float u = t - floorf(t);
    float pf = floorf((s + 4.0f) * 3.75f + 1.0f);
    if (s <= -4.0f) pf = 1.0f;
    if (s >=  4.0f) pf = 31.0f;
    int p0 = (int)pf;
    p0 = max(1, min(31, p0));
    float Q0 = q[p0 - 1];
    float Q1 = q[p0];
    float Q2 = q[p0 + 1];
    float Q3 = q[p0 + 2];
    float c3 = 3.0f * (Q1 - Q2) + (Q3 - Q0);
    float c2 = 2.0f * Q0 - 5.0f * Q1 + 4.0f * Q2 - Q3;
    float c1 = Q2 - Q0;
    float c0 = 2.0f * Q1;
    return 0.5f * (((c3 * u + c2) * u + c1) * u + c0);
}

__device__ __forceinline__ void mbar_init(uint32_t mbar, uint32_t cnt) {
    asm volatile("mbarrier.init.shared.b64 [%0], %1;" :: "r"(mbar), "r"(cnt) : "memory");
}
__device__ __forceinline__ void mbar_expect(uint32_t mbar, uint32_t bytes) {
    asm volatile("mbarrier.arrive.expect_tx.shared.b64 _, [%0], %1;" :: "r"(mbar), "r"(bytes) : "memory");
}
__device__ __forceinline__ void mbar_arrive(uint32_t mbar) {
    asm volatile("mbarrier.arrive.shared.b64 _, [%0];" :: "r"(mbar) : "memory");
}
__device__ __forceinline__ void mbar_wait_acq(uint32_t mbar, uint32_t parity) {
    asm volatile(
        "{\n\t.reg .pred P;\n\t"
        "LW%=:\n\t"
        "mbarrier.try_wait.parity.acquire.cta.shared::cta.b64 P, [%0], %1, 0x989680;\n\t"
        "@P bra.uni LD%=;\n\t"
        "bra.uni LW%=;\n\t"
        "LD%=:\n\t}"
        :: "r"(mbar), "r"(parity) : "memory");
}
__device__ __forceinline__ void mbar_wait_rlx(uint32_t mbar, uint32_t parity) {
    asm volatile(
        "{\n\t.reg .pred P;\n\t"
        "LW%=:\n\t"
        "mbarrier.try_wait.parity.relaxed.cta.shared::cta.b64 P, [%0], %1, 0x989680;\n\t"
        "@P bra.uni LD%=;\n\t"
        "bra.uni LW%=;\n\t"
        "LD%=:\n\t}"
        :: "r"(mbar), "r"(parity) : "memory");
}
__device__ __forceinline__ void bulk_g2s(uint32_t dst, const void* src, uint32_t bytes, uint32_t mbar) {
    asm volatile("cp.async.bulk.shared::cluster.global.mbarrier::complete_tx::bytes [%0], [%1], %2, [%3];"
                 :: "r"(dst), "l"(src), "r"(bytes), "r"(mbar) : "memory");
}

__global__ __launch_bounds__(256, 2) void gemm_spline(const float* __restrict__ CP,
                                                      float* __restrict__ out)
{
    extern __shared__ char smem[];
    const uint32_t su = s2u(smem);
    const uint32_t FULL  = su + SOFF_MBAR;        // +8*s
    const uint32_t EMPTY = su + SOFF_MBAR + 24;   // +8*s

    const int tid  = threadIdx.x;
    const int lane = tid & 31;
    const int wid  = tid >> 5;
    const int bx = blockIdx.x;   // n tile (0..7)
    const int by = blockIdx.y;   // m tile (0..127)

    const char* Ag = reinterpret_cast<const char*>(A3_buf) + (size_t)by * 32 * TILE_BYTES;
    const char* Bg = reinterpret_cast<const char*>(B3_buf) + (size_t)bx * 32 * TILE_BYTES;

    if (tid == 0) {
        #pragma unroll
        for (int s = 0; s < 3; ++s) {
            mbar_init(FULL + 8 * s, 1);
            mbar_init(EMPTY + 8 * s, 8);
        }
        asm volatile("fence.proxy.async;" ::: "memory");
        #pragma unroll
        for (int s = 0; s < 3; ++s) {   // prologue: chunks 0..2
            mbar_expect(FULL + 8 * s, 2 * TILE_BYTES);
            bulk_g2s(su + SOFF_A + s * TILE_BYTES, Ag + (size_t)s * TILE_BYTES, TILE_BYTES, FULL + 8 * s);
            bulk_g2s(su + SOFF_B + s * TILE_BYTES, Bg + (size_t)s * TILE_BYTES, TILE_BYTES, FULL + 8 * s);
        }
    }
    __syncthreads();   // mbarrier init visible

    float4 acc[4][4];
    #pragma unroll
    for (int i = 0; i < 4; ++i)
        #pragma unroll
        for (int j = 0; j < 4; ++j)
            acc[i][j] = make_float4(0.f, 0.f, 0.f, 0.f);

    const int mw = (wid >> 2) * 64;
    const int nw = (wid & 3) * 32;
    const int lrow = lane & 15;
    const int lcol = lane >> 4;
    const int xk = lrow & 7;
    const uint32_t g_h[2] = { (uint32_t)(((0 + lcol) ^ xk) * 16), (uint32_t)(((2 + lcol) ^ xk) * 16) };
    const uint32_t g_l[2] = { (uint32_t)(((4 + lcol) ^ xk) * 16), (uint32_t)(((6 + lcol) ^ xk) * 16) };
    const uint32_t aRowB = su + SOFF_A + (mw + lrow) * 128;
    const uint32_t bRowB = su + SOFF_B + (nw + lrow) * 128;

    // R10 chunk structure: wait FULL -> LDSM/MMA ks0 -> LDSM ks1 -> arrive EMPTY
    // -> MMA ks1 -> producer refill (lookahead +3).
    #define DO_CHUNK(S, CIDX, PH)                                                        \
    {                                                                                    \
        mbar_wait_acq(FULL + 8 * (S), (PH));                                             \
        const uint32_t aRow = aRowB + (S) * TILE_BYTES;                                  \
        const uint32_t bRow = bRowB + (S) * TILE_BYTES;                                  \
        uint32_t Ah0[4][4], Al0[4][4], Bh0[2][4], Bl0[2][4];                             \
        _Pragma("unroll")                                                                \
        for (int mf = 0; mf < 4; ++mf) {                                                 \
            LDSM4(Ah0[mf], aRow + mf * (16 * 128) + g_h[0]);                             \
            LDSM4(Al0[mf], aRow + mf * (16 * 128) + g_l[0]);                             \
        }                                                                                \
        _Pragma("unroll")                                                                \
        for (int g = 0; g < 2; ++g) {                                                    \
            LDSM4(Bh0[g], bRow + g * (16 * 128) + g_h[0]);                               \
            LDSM4(Bl0[g], bRow + g * (16 * 128) + g_l[0]);                               \
        }                                                                                \
        _Pragma("unroll")                                                                \
        for (int mf = 0; mf < 4; ++mf)                                                   \
            _Pragma("unroll")                                                            \
            for (int nf = 0; nf < 4; ++nf) {                                             \
                const int g = nf >> 1, w = nf & 1;                                       \
                MMA16816(acc[mf][nf], Ah0[mf], Bh0[g][w], Bh0[g][w + 2]);                \
                MMA16816(acc[mf][nf], Al0[mf], Bh0[g][w], Bh0[g][w + 2]);                \
                MMA16816(acc[mf][nf], Ah0[mf], Bl0[g][w], Bl0[g][w + 2]);                \
            }                                                                            \
        uint32_t Ah1[4][4], Al1[4][4], Bh1[2][4], Bl1[2][4];                             \
        _Pragma("unroll")                                                                \
        for (int mf = 0; mf < 4; ++mf) {                                                 \
            LDSM4(Ah1[mf], aRow + mf * (16 * 128) + g_h[1]);                             \
            LDSM4(Al1[mf], aRow + mf * (16 * 128) + g_l[1]);                             \
        }                                                                                \
        _Pragma("unroll")                                                                \
        for (int g = 0; g < 2; ++g) {                                                    \
            LDSM4(Bh1[g], bRow + g * (16 * 128) + g_h[1]);                               \
            LDSM4(Bl1[g], bRow + g * (16 * 128) + g_l[1]);                               \
        }                                                                                \
        if (lane == 0) mbar_arrive(EMPTY + 8 * (S));   /* all smem reads issued */       \
        _Pragma("unroll")                                                                \
        for (int mf = 0; mf < 4; ++mf)                                                   \
            _Pragma("unroll")                                                            \
            for (int nf = 0; nf < 4; ++nf) {                                             \
                const int g = nf >> 1, w = nf & 1;                                       \
                MMA16816(acc[mf][nf], Ah1[mf], Bh1[g][w], Bh1[g][w + 2]);                \
                MMA16816(acc[mf][nf], Al1[mf], Bh1[g][w], Bh1[g][w + 2]);                \
                MMA16816(acc[mf][nf], Ah1[mf], Bl1[g][w], Bl1[g][w + 2]);                \
            }                                                                            \
        if (tid == 0 && (CIDX) + 3 < 32) {                                               \
            mbar_wait_rlx(EMPTY + 8 * (S), (PH));                                        \
            mbar_expect(FULL + 8 * (S), 2 * TILE_BYTES);                                 \
            bulk_g2s(su + SOFF_A + (S) * TILE_BYTES,                                     \
                     Ag + (size_t)((CIDX) + 3) * TILE_BYTES, TILE_BYTES, FULL + 8 * (S));\
            bulk_g2s(su + SOFF_B + (S) * TILE_BYTES,                                     \
                     Bg + (size_t)((CIDX) + 3) * TILE_BYTES, TILE_BYTES, FULL + 8 * (S));\
        }                                                                                \
    }

    // 32 chunks = 10 rounds of 3 + chunks 30,31 (stage occurrence parities: i&1).
    #pragma unroll 1
    for (int p = 0; p < 10; ++p) {
        const uint32_t ph = (uint32_t)(p & 1);
        DO_CHUNK(0, 3 * p,     ph)
        DO_CHUNK(1, 3 * p + 1, ph)
        DO_CHUNK(2, 3 * p + 2, ph)
    }
    DO_CHUNK(0, 30, 0)
    DO_CHUNK(1, 31, 0)
    #undef DO_CHUNK

    // Mainloop done: overlay control points onto the stage-A smem region.
    __syncthreads();
    float* cps = reinterpret_cast<float*>(smem);
    for (int i = tid; i < 128 * KCP; i += 256) {
        int c = i / KCP, k = i - c * KCP;
        cps[c * 35 + k] = CP[(size_t)(bx * 128 + c) * KCP + k];
    }
    __syncthreads();

    // epilogue: spline + store
    #pragma unroll
    for (int mf = 0; mf < 4; ++mf) {
        const int row0 = mw + mf * 16 + (lane >> 2);
        const size_t g0 = (size_t)(by * 128 + row0) * NN + bx * 128;
        const size_t g1 = g0 + 8 * NN;
        #pragma unroll
        for (int nf = 0; nf < 4; ++nf) {
            const int cl = nw + nf * 8 + 2 * (lane & 3);
            const float* q0 = &cps[cl * 35];
            const float* q1 = &cps[(cl + 1) * 35];
            float2 o0, o1;
            o0.x = spline_eval(acc[mf][nf].x, q0);
            o0.y = spline_eval(acc[mf][nf].y, q1);
            o1.x = spline_eval(acc[mf][nf].z, q0);
            o1.y = spline_eval(acc[mf][nf].w, q1);
            *reinterpret_cast<float2*>(out + g0 + cl) = o0;
            *reinterpret_cast<float2*>(out + g1 + cl) = o1;
        }
    }
}

extern "C" void kernel_launch(void* const* d_in, const int* in_sizes, int n_in,
                              void* d_out, int out_size)
{
    const float* X  = (const float*)d_in[0];
    const float* W  = (const float*)d_in[1];
    const float* CP = (const float*)d_in[2];
    float* out = (float*)d_out;

    cudaFuncSetAttribute(gemm_spline, cudaFuncAttributeMaxDynamicSharedMemorySize, SMEM_TOTAL);

    convert_A<<<(MM * 128) / 256, 256>>>(X);
    convert_B<<<(NN * 128) / 256, 256>>>(W);

    dim3 grid(NN / 128, MM / 128);   // (8, 128)
    gemm_spline<<<grid, 256, SMEM_TOTAL>>>(CP, out);
}